// round 3
// baseline (speedup 1.0000x reference)
#include <cuda_runtime.h>

// Problem constants (fixed by the dataset)
#define BSZ   32
#define NTGT  64
#define NCLS  4
#define RM    16
#define NLVL  4

// Scratch accumulators (no allocation allowed -> __device__ globals)
__device__ float g_base[NLVL * BSZ];   // sum over HW of (lse - logit0) per (level, batch)
__device__ float g_adj;                // sum of adj over valid targets, all levels
__device__ float g_box;                // sum of box_per over valid targets, all levels
__device__ float g_dfl;                // sum of dfl_per over valid targets, all levels

// ---------------------------------------------------------------------------
__global__ void yolo_init_kernel() {
    int i = threadIdx.x;
    if (i < NLVL * BSZ) g_base[i] = 0.0f;
    if (i == NLVL * BSZ + 0) g_adj = 0.0f;
    if (i == NLVL * BSZ + 1) g_box = 0.0f;
    if (i == NLVL * BSZ + 2) g_dfl = 0.0f;
}

// ---------------------------------------------------------------------------
// Streaming logsumexp pass over one FPN level's cls tensor.
// The reference reshapes [B, nc, H, W] -> [B, H*W, nc], which reinterprets the
// contiguous buffer as HW rows of nc=4 floats -> one float4 per cell.
// Grid: exactly B*HW/256 blocks; HW is a multiple of 256 at every level, so a
// block never straddles a batch boundary.
__global__ void yolo_base_kernel(const float4* __restrict__ cls, int HW, int lvl) {
    __shared__ float sdata[256];
    int idx = blockIdx.x * 256 + threadIdx.x;   // global cell index in [0, B*HW)
    float4 v = cls[idx];
    float m = fmaxf(fmaxf(v.x, v.y), fmaxf(v.z, v.w));
    float e = expf(v.x - m) + expf(v.y - m) + expf(v.z - m) + expf(v.w - m);
    float val = m + logf(e) - v.x;              // lse - logits[...,0]

    sdata[threadIdx.x] = val;
    __syncthreads();
    for (int off = 128; off > 0; off >>= 1) {
        if (threadIdx.x < off) sdata[threadIdx.x] += sdata[threadIdx.x + off];
        __syncthreads();
    }
    if (threadIdx.x == 0) {
        int b = idx / HW;                       // same for whole block
        atomicAdd(&g_base[lvl * BSZ + b], sdata[0]);
    }
}

// ---------------------------------------------------------------------------
// One warp per (level, batch, target) item: 4*32*64 = 8192 items.
// Lane l reads reg channels c = l and c = l+32; shuffle reductions produce
// the per-4-bin means (box) and the L1 sums (dfl). Lane 0 also computes adj.
__global__ void yolo_target_kernel(
    const float* __restrict__ c0, const float* __restrict__ c1,
    const float* __restrict__ c2, const float* __restrict__ c3,
    const float* __restrict__ r0, const float* __restrict__ r1,
    const float* __restrict__ r2, const float* __restrict__ r3,
    const float* __restrict__ targets)
{
    __shared__ float sadj[8], sbox[8], sdfl[8];

    int gwarp = (blockIdx.x * blockDim.x + threadIdx.x) >> 5;  // 0..8191
    int lane  = threadIdx.x & 31;
    int warpInBlk = threadIdx.x >> 5;

    int lvl = gwarp >> 11;          // /2048
    int rem = gwarp & 2047;
    int b   = rem >> 6;
    int n   = rem & 63;

    const float* clsArr[NLVL] = {c0, c1, c2, c3};
    const float* regArr[NLVL] = {r0, r1, r2, r3};
    const int   Wlut[NLVL] = {128, 64, 32, 16};
    const float Slut[NLVL] = {8.f, 16.f, 32.f, 64.f};

    const float* tg = targets + (b * NTGT + n) * 5;
    float t0 = tg[0], x1 = tg[1], y1 = tg[2], x2 = tg[3], y2 = tg[4];
    bool valid = (t0 >= 0.0f);
    int cid = (int)fmaxf(t0, 0.0f);
    cid = min(max(cid, 0), NCLS - 1);

    float cx = (x1 + x2) * 0.5f;
    float cy = (y1 + y2) * 0.5f;
    int   W  = Wlut[lvl];
    float s  = Slut[lvl];
    int   HW = W * W;
    float inv_s = 1.0f / s;

    int gx = (int)(cx * inv_s);  gx = min(max(gx, 0), W - 1);   // trunc == floor (cx>0)
    int gy = (int)(cy * inv_s);  gy = min(max(gy, 0), W - 1);
    int cell = gy * W + gx;

    float treg[4];
    treg[0] = (cx - (float)gx * s) * inv_s;
    treg[1] = (cy - (float)gy * s) * inv_s;
    treg[2] = (x2 - x1) * inv_s;
    treg[3] = (y2 - y1) * inv_s;

    // Gather reg predictions: rp[b, c, gy, gx], c = lane and lane+32
    const float* rp = regArr[lvl] + (size_t)b * 64 * HW + cell;
    float p0 = rp[(size_t)lane * HW];
    float p1 = rp[(size_t)(lane + 32) * HW];

    int jA = lane >> 4;       // 0 for lanes 0..15, 1 for 16..31
    int jB = jA + 2;          // 2 / 3

    // DFL: sum |pred - treg| over all 64 entries
    float dflp = fabsf(p0 - treg[jA]) + fabsf(p1 - treg[jB]);
    #pragma unroll
    for (int off = 16; off > 0; off >>= 1)
        dflp += __shfl_xor_sync(0xffffffffu, dflp, off);

    // Box: per-16-lane-group sums -> means
    float s0 = p0, s1 = p1;
    #pragma unroll
    for (int off = 8; off > 0; off >>= 1) {
        s0 += __shfl_xor_sync(0xffffffffu, s0, off, 16);
        s1 += __shfl_xor_sync(0xffffffffu, s1, off, 16);
    }
    float bp = 0.0f;
    if ((lane & 15) == 0) {   // lanes 0 and 16 hold group sums (j=0/2 and j=1/3)
        bp = fabsf(s0 * (1.0f / RM) - treg[jA]) + fabsf(s1 * (1.0f / RM) - treg[jB]);
    }
    bp += __shfl_xor_sync(0xffffffffu, bp, 16);

    float item_adj = 0.0f, item_box = 0.0f, item_dfl = 0.0f;
    if (lane == 0 && valid) {
        // adj = (logits[b,t,0] - logits[b,t,cid]) / HW using the reshape layout
        const float* cp = clsArr[lvl] + (size_t)b * NCLS * HW + (size_t)cell * NCLS;
        item_adj = (cp[0] - cp[cid]) / (float)HW;
        item_box = bp * 0.25f;
        item_dfl = dflp * (1.0f / 64.0f);
    }

    if (lane == 0) {
        sadj[warpInBlk] = item_adj;
        sbox[warpInBlk] = item_box;
        sdfl[warpInBlk] = item_dfl;
    }
    __syncthreads();
    if (threadIdx.x == 0) {
        float a = 0.f, bx = 0.f, d = 0.f;
        #pragma unroll
        for (int i = 0; i < 8; i++) { a += sadj[i]; bx += sbox[i]; d += sdfl[i]; }
        atomicAdd(&g_adj, a);
        atomicAdd(&g_box, bx);
        atomicAdd(&g_dfl, d);
    }
}

// ---------------------------------------------------------------------------
__global__ void yolo_finalize_kernel(const float* __restrict__ targets,
                                     float* __restrict__ out) {
    __shared__ float nvalid[BSZ];
    __shared__ float sred[128];
    int tid = threadIdx.x;

    if (tid < BSZ) {
        int cnt = 0;
        for (int n = 0; n < NTGT; n++)
            cnt += (targets[(tid * NTGT + n) * 5] >= 0.0f) ? 1 : 0;
        nvalid[tid] = (float)cnt;
    }
    __syncthreads();

    float part = 0.0f;
    if (tid < NLVL * BSZ) {
        int lvl = tid >> 5;
        int b   = tid & 31;
        const float invHW[NLVL] = {1.f / 16384.f, 1.f / 4096.f, 1.f / 1024.f, 1.f / 256.f};
        part = g_base[tid] * invHW[lvl] * nvalid[b];
    }
    sred[tid] = part;
    __syncthreads();
    for (int off = 64; off > 0; off >>= 1) {
        if (tid < off) sred[tid] += sred[tid + off];
        __syncthreads();
    }
    if (tid == 0) {
        float cls = sred[0] + g_adj;
        float box = g_box;
        float dfl = g_dfl;
        out[0] = 0.3f * cls + 8.0f * box + 1.5f * dfl;
        out[1] = cls;
        out[2] = box;
        out[3] = dfl;
    }
}

// ---------------------------------------------------------------------------
extern "C" void kernel_launch(void* const* d_in, const int* in_sizes, int n_in,
                              void* d_out, int out_size) {
    const float* cls[NLVL];
    const float* reg[NLVL];

    // Disambiguate input ordering at runtime:
    //   signature order: cls_p3..cls_p6, reg_p3..reg_p6, targets
    //     -> in_sizes[0]=2097152 (cls_p3), in_sizes[1]=524288 (cls_p4)  [1]<[0]
    //   interleaved (setup_inputs dict) order: cls_p3, reg_p3, cls_p4, reg_p4, ...
    //     -> in_sizes[0]=2097152 (cls_p3), in_sizes[1]=33554432 (reg_p3) [1]>[0]
    bool interleaved = (in_sizes[1] > in_sizes[0]);
    if (interleaved) {
        for (int l = 0; l < NLVL; l++) {
            cls[l] = (const float*)d_in[2 * l];
            reg[l] = (const float*)d_in[2 * l + 1];
        }
    } else {
        for (int l = 0; l < NLVL; l++) {
            cls[l] = (const float*)d_in[l];
            reg[l] = (const float*)d_in[NLVL + l];
        }
    }
    const float* targets = (const float*)d_in[8];
    float* out = (float*)d_out;

    yolo_init_kernel<<<1, 256>>>();

    const int HWs[NLVL] = {128 * 128, 64 * 64, 32 * 32, 16 * 16};
    for (int l = 0; l < NLVL; l++) {
        int cells = BSZ * HWs[l];
        yolo_base_kernel<<<cells / 256, 256>>>((const float4*)cls[l], HWs[l], l);
    }

    // 8192 warp-items, 8 warps per block -> 1024 blocks
    yolo_target_kernel<<<1024, 256>>>(cls[0], cls[1], cls[2], cls[3],
                                      reg[0], reg[1], reg[2], reg[3], targets);

    yolo_finalize_kernel<<<1, 128>>>(targets, out);
}

// round 4
// speedup vs baseline: 1.9030x; 1.9030x over previous
#include <cuda_runtime.h>

#define BSZ   32
#define NTGT  64
#define NCLS  4
#define RM    16
#define NLVL  4

// Block layout: base blocks then target blocks
#define NB_L0   512     // 32*16384 cells / 1024 cells-per-block
#define NB_L1   128     // 32*4096 / 1024
#define NB_L2   32      // 32*1024 / 1024
#define NB_L3   32      // 32*256  / 256
#define NB_BASE (NB_L0 + NB_L1 + NB_L2 + NB_L3)   // 704
#define NB_TGT  1024    // 8192 warp-items / 8 warps per block
#define NB_TOT  (NB_BASE + NB_TGT)                // 1728

#define NSLOT 32

// Scratch (zero-initialized at module load; finalize resets after each run)
__device__ float        g_base[NLVL * BSZ];
__device__ float        g_adjS[NSLOT];
__device__ float        g_boxS[NSLOT];
__device__ float        g_dflS[NSLOT];
__device__ unsigned int g_count;

__constant__ float c_invHW[NLVL] = {1.f/16384.f, 1.f/4096.f, 1.f/1024.f, 1.f/256.f};

__device__ __forceinline__ float lse4(float4 v) {
    float m = fmaxf(fmaxf(v.x, v.y), fmaxf(v.z, v.w));
    float e = __expf(v.x - m) + __expf(v.y - m) + __expf(v.z - m) + __expf(v.w - m);
    return m + __logf(e) - v.x;    // lse - logits[...,0]
}

__global__ void __launch_bounds__(256) yolo_fused_kernel(
    const float* __restrict__ c0, const float* __restrict__ c1,
    const float* __restrict__ c2, const float* __restrict__ c3,
    const float* __restrict__ r0, const float* __restrict__ r1,
    const float* __restrict__ r2, const float* __restrict__ r3,
    const float* __restrict__ targets, float* __restrict__ out)
{
    __shared__ float s24[24];
    __shared__ float fnv[BSZ];
    __shared__ int   s_last;

    int bid  = blockIdx.x;
    int tid  = threadIdx.x;
    int lane = tid & 31;
    int wrp  = tid >> 5;

    if (bid < NB_BASE) {
        // ---------------- base: streaming logsumexp over cls ----------------
        float sum = 0.0f;
        int gidx;   // lvl*32 + b
        if (bid < NB_L0 + NB_L1 + NB_L2) {
            int lvl, bloc;
            const float* cp;
            if (bid < NB_L0)              { lvl = 0; bloc = bid;              cp = c0; }
            else if (bid < NB_L0 + NB_L1) { lvl = 1; bloc = bid - NB_L0;      cp = c1; }
            else                          { lvl = 2; bloc = bid - NB_L0-NB_L1; cp = c2; }
            const float4* v4 = (const float4*)cp;
            int start = bloc << 10;                       // 1024 cells per block
            float4 va = v4[start + tid];
            float4 vb = v4[start + 256 + tid];
            float4 vc = v4[start + 512 + tid];
            float4 vd = v4[start + 768 + tid];
            sum = lse4(va) + lse4(vb) + lse4(vc) + lse4(vd);
            int hwlog = (lvl == 0) ? 14 : ((lvl == 1) ? 12 : 10);
            gidx = (lvl << 5) + (start >> hwlog);
        } else {
            int bloc = bid - (NB_L0 + NB_L1 + NB_L2);     // 0..31, one batch each
            float4 v = ((const float4*)c3)[(bloc << 8) + tid];
            sum = lse4(v);
            gidx = (3 << 5) + bloc;
        }
        #pragma unroll
        for (int off = 16; off > 0; off >>= 1)
            sum += __shfl_xor_sync(0xffffffffu, sum, off);
        if (lane == 0) s24[wrp] = sum;
        __syncthreads();
        if (tid == 0) {
            float t = 0.f;
            #pragma unroll
            for (int i = 0; i < 8; i++) t += s24[i];
            atomicAdd(&g_base[gidx], t);
        }
    } else {
        // ---------------- target: one warp per (lvl, b, n) ----------------
        int gwarp = (bid - NB_BASE) * 8 + wrp;            // 0..8191
        int lvl = gwarp >> 11;
        int rem = gwarp & 2047;
        int b   = rem >> 6;
        int n   = rem & 63;

        const float* cp = (lvl == 0) ? c0 : (lvl == 1) ? c1 : (lvl == 2) ? c2 : c3;
        const float* rp0 = (lvl == 0) ? r0 : (lvl == 1) ? r1 : (lvl == 2) ? r2 : r3;
        int   W = 128 >> lvl;
        float s = 8.0f * (float)(1 << lvl);
        int   HW = W * W;
        float inv_s = 1.0f / s;

        const float* tg = targets + (b * NTGT + n) * 5;
        float t0 = tg[0], x1 = tg[1], y1 = tg[2], x2 = tg[3], y2 = tg[4];
        bool valid = (t0 >= 0.0f);
        int cid = min(max((int)fmaxf(t0, 0.0f), 0), NCLS - 1);

        float cx = (x1 + x2) * 0.5f;
        float cy = (y1 + y2) * 0.5f;
        int gx = min(max((int)(cx * inv_s), 0), W - 1);
        int gy = min(max((int)(cy * inv_s), 0), W - 1);
        int cell = gy * W + gx;

        float tr0 = (cx - (float)gx * s) * inv_s;
        float tr1 = (cy - (float)gy * s) * inv_s;
        float tr2 = (x2 - x1) * inv_s;
        float tr3 = (y2 - y1) * inv_s;

        const float* rp = rp0 + (size_t)b * 64 * HW + cell;
        float p0 = rp[(size_t)lane * HW];
        float p1 = rp[(size_t)(lane + 32) * HW];

        float tA = (lane < 16) ? tr0 : tr1;
        float tB = (lane < 16) ? tr2 : tr3;

        float dflp = fabsf(p0 - tA) + fabsf(p1 - tB);
        #pragma unroll
        for (int off = 16; off > 0; off >>= 1)
            dflp += __shfl_xor_sync(0xffffffffu, dflp, off);

        float s0 = p0, s1 = p1;
        #pragma unroll
        for (int off = 8; off > 0; off >>= 1) {
            s0 += __shfl_xor_sync(0xffffffffu, s0, off, 16);
            s1 += __shfl_xor_sync(0xffffffffu, s1, off, 16);
        }
        float bp = 0.0f;
        if ((lane & 15) == 0)
            bp = fabsf(s0 * (1.0f / RM) - tA) + fabsf(s1 * (1.0f / RM) - tB);
        bp += __shfl_xor_sync(0xffffffffu, bp, 16);

        float ia = 0.f, ib = 0.f, id = 0.f;
        if (lane == 0 && valid) {
            const float* cc = cp + (size_t)b * NCLS * HW + (size_t)cell * NCLS;
            ia = (cc[0] - cc[cid]) / (float)HW;
            ib = bp * 0.25f;
            id = dflp * (1.0f / 64.0f);
        }
        if (lane == 0) { s24[wrp] = ia; s24[8 + wrp] = ib; s24[16 + wrp] = id; }
        __syncthreads();
        if (tid == 0) {
            float a = 0.f, bb = 0.f, d = 0.f;
            #pragma unroll
            for (int i = 0; i < 8; i++) { a += s24[i]; bb += s24[8+i]; d += s24[16+i]; }
            int slot = bid & (NSLOT - 1);
            atomicAdd(&g_adjS[slot], a);
            atomicAdd(&g_boxS[slot], bb);
            atomicAdd(&g_dflS[slot], d);
        }
    }

    // ---------------- grid-completion handshake ----------------
    __syncthreads();
    __threadfence();
    if (tid == 0) {
        unsigned int old = atomicAdd(&g_count, 1u);
        s_last = (old == NB_TOT - 1) ? 1 : 0;
    }
    __syncthreads();
    if (!s_last) return;

    // ---------------- finalize (last block only) ----------------
    if (tid < BSZ) {
        int cnt = 0;
        for (int n = 0; n < NTGT; n++)
            cnt += (targets[(tid * NTGT + n) * 5] >= 0.0f) ? 1 : 0;
        fnv[tid] = (float)cnt;
    }
    __syncthreads();

    float clsP = 0.f, boxP = 0.f, dflP = 0.f;
    if (tid < NLVL * BSZ)
        clsP = __ldcg(&g_base[tid]) * c_invHW[tid >> 5] * fnv[tid & 31];
    else if (tid < NLVL * BSZ + NSLOT)
        clsP = __ldcg(&g_adjS[tid - NLVL * BSZ]);
    if (tid < NSLOT) {
        boxP = __ldcg(&g_boxS[tid]);
        dflP = __ldcg(&g_dflS[tid]);
    }
    #pragma unroll
    for (int off = 16; off > 0; off >>= 1) {
        clsP += __shfl_xor_sync(0xffffffffu, clsP, off);
        boxP += __shfl_xor_sync(0xffffffffu, boxP, off);
        dflP += __shfl_xor_sync(0xffffffffu, dflP, off);
    }
    if (lane == 0) { s24[wrp] = clsP; s24[8 + wrp] = boxP; s24[16 + wrp] = dflP; }
    __syncthreads();
    if (tid == 0) {
        float cls = 0.f, box = 0.f, dfl = 0.f;
        #pragma unroll
        for (int i = 0; i < 8; i++) { cls += s24[i]; box += s24[8+i]; dfl += s24[16+i]; }
        out[0] = 0.3f * cls + 8.0f * box + 1.5f * dfl;
        out[1] = cls;
        out[2] = box;
        out[3] = dfl;
        g_count = 0u;
    }
    // reset scratch for the next replay
    if (tid < NLVL * BSZ) g_base[tid] = 0.0f;
    if (tid < NSLOT) { g_adjS[tid] = 0.0f; g_boxS[tid] = 0.0f; g_dflS[tid] = 0.0f; }
}

// ---------------------------------------------------------------------------
extern "C" void kernel_launch(void* const* d_in, const int* in_sizes, int n_in,
                              void* d_out, int out_size) {
    const float* cls[NLVL];
    const float* reg[NLVL];
    // Runtime disambiguation of input ordering (see R2 note):
    bool interleaved = (in_sizes[1] > in_sizes[0]);
    if (interleaved) {
        for (int l = 0; l < NLVL; l++) {
            cls[l] = (const float*)d_in[2 * l];
            reg[l] = (const float*)d_in[2 * l + 1];
        }
    } else {
        for (int l = 0; l < NLVL; l++) {
            cls[l] = (const float*)d_in[l];
            reg[l] = (const float*)d_in[NLVL + l];
        }
    }
    const float* targets = (const float*)d_in[8];
    float* out = (float*)d_out;

    yolo_fused_kernel<<<NB_TOT, 256>>>(cls[0], cls[1], cls[2], cls[3],
                                       reg[0], reg[1], reg[2], reg[3],
                                       targets, out);
}

// round 5
// speedup vs baseline: 2.1695x; 1.1400x over previous
#include <cuda_runtime.h>

#define BSZ   32
#define NTGT  64
#define NCLS  4
#define RM    16
#define NLVL  4

// Single-wave grid layout
#define NB_L0   256    // 32*16384 cells / 2048 cells-per-block
#define NB_L1   64     // 32*4096  / 2048
#define NB_L2   32     // 32*1024  / 1024
#define NB_L3   32     // 32*256   / 256
#define NB_BASE (NB_L0 + NB_L1 + NB_L2 + NB_L3)   // 384
#define NB_TGT  512    // 8192 items / (8 warps * 2 items)
#define NB_TOT  (NB_BASE + NB_TGT)                // 896

#define NSLOT 32

// Scratch (zero at module load; finalize resets after each run)
__device__ float        g_base[NLVL * BSZ];
__device__ float        g_adjS[NSLOT];
__device__ float        g_boxS[NSLOT];
__device__ float        g_dflS[NSLOT];
__device__ unsigned int g_count;

__constant__ float c_invHW[NLVL] = {1.f/16384.f, 1.f/4096.f, 1.f/1024.f, 1.f/256.f};

// lse - logits[0] without max-subtraction: args bounded (inputs ~N(0,1)).
// 3 exp + 1 log MUFU ops instead of 4 exp + 1 log + 3 fmax.
__device__ __forceinline__ float lse4(float4 v) {
    float e = __expf(v.y - v.x) + __expf(v.z - v.x) + __expf(v.w - v.x);
    return __logf(1.0f + e);
}

__global__ void __launch_bounds__(256) yolo_fused_kernel(
    const float* __restrict__ c0, const float* __restrict__ c1,
    const float* __restrict__ c2, const float* __restrict__ c3,
    const float* __restrict__ r0, const float* __restrict__ r1,
    const float* __restrict__ r2, const float* __restrict__ r3,
    const float* __restrict__ targets, float* __restrict__ out)
{
    __shared__ float s24[24];
    __shared__ float fnv[BSZ];
    __shared__ int   s_last;

    int bid  = blockIdx.x;
    int tid  = threadIdx.x;
    int lane = tid & 31;
    int wrp  = tid >> 5;

    if (bid < NB_BASE) {
        // ---------------- base: streaming logsumexp over cls ----------------
        float sum = 0.0f;
        int gidx;   // lvl*32 + b
        if (bid < NB_L0) {                      // L0: 2048 cells, 8/thread
            const float4* v4 = (const float4*)c0;
            int start = bid << 11;
            #pragma unroll
            for (int i = 0; i < 8; i++) sum += lse4(v4[start + (i << 8) + tid]);
            gidx = bid >> 3;                    // 8 blocks per batch
        } else if (bid < NB_L0 + NB_L1) {       // L1: 2048 cells, 8/thread
            const float4* v4 = (const float4*)c1;
            int bl = bid - NB_L0;
            int start = bl << 11;
            #pragma unroll
            for (int i = 0; i < 8; i++) sum += lse4(v4[start + (i << 8) + tid]);
            gidx = 32 + (bl >> 1);              // 2 blocks per batch
        } else if (bid < NB_L0 + NB_L1 + NB_L2) { // L2: 1024 cells, 4/thread
            const float4* v4 = (const float4*)c2;
            int bl = bid - NB_L0 - NB_L1;
            int start = bl << 10;
            #pragma unroll
            for (int i = 0; i < 4; i++) sum += lse4(v4[start + (i << 8) + tid]);
            gidx = 64 + bl;                     // 1 block per batch
        } else {                                // L3: 256 cells, 1/thread
            const float4* v4 = (const float4*)c3;
            int bl = bid - NB_L0 - NB_L1 - NB_L2;
            sum = lse4(v4[(bl << 8) + tid]);
            gidx = 96 + bl;
        }
        #pragma unroll
        for (int off = 16; off > 0; off >>= 1)
            sum += __shfl_xor_sync(0xffffffffu, sum, off);
        if (lane == 0) s24[wrp] = sum;
        __syncthreads();
        if (tid == 0) {
            float t = 0.f;
            #pragma unroll
            for (int i = 0; i < 8; i++) t += s24[i];
            atomicAdd(&g_base[gidx], t);
        }
    } else {
        // -------- target: one warp handles TWO (lvl, b, n) items --------
        int gw  = (bid - NB_BASE) * 8 + wrp;    // 0..4095
        int lvl = gw >> 10;
        int rr  = gw & 1023;                    // itemA: rem=rr; itemB: rem=rr+1024
        int b0  = rr >> 6;                      // itemB batch = b0 + 16
        int n   = rr & 63;

        const float* cp  = (lvl == 0) ? c0 : (lvl == 1) ? c1 : (lvl == 2) ? c2 : c3;
        const float* rp0 = (lvl == 0) ? r0 : (lvl == 1) ? r1 : (lvl == 2) ? r2 : r3;
        int   W = 128 >> lvl;
        float s = 8.0f * (float)(1 << lvl);
        int   HW = W * W;
        float inv_s = 1.0f / s;

        // decode both targets
        const float* tgA = targets + (b0 * NTGT + n) * 5;
        const float* tgB = tgA + 16 * NTGT * 5;
        float tA0 = tgA[0], ax1 = tgA[1], ay1 = tgA[2], ax2 = tgA[3], ay2 = tgA[4];
        float tB0 = tgB[0], bx1 = tgB[1], by1 = tgB[2], bx2 = tgB[3], by2 = tgB[4];
        bool vA = (tA0 >= 0.0f), vB = (tB0 >= 0.0f);
        int cidA = min(max((int)fmaxf(tA0, 0.0f), 0), NCLS - 1);
        int cidB = min(max((int)fmaxf(tB0, 0.0f), 0), NCLS - 1);

        float cxA = (ax1 + ax2) * 0.5f, cyA = (ay1 + ay2) * 0.5f;
        float cxB = (bx1 + bx2) * 0.5f, cyB = (by1 + by2) * 0.5f;
        int gxA = min(max((int)(cxA * inv_s), 0), W - 1);
        int gyA = min(max((int)(cyA * inv_s), 0), W - 1);
        int gxB = min(max((int)(cxB * inv_s), 0), W - 1);
        int gyB = min(max((int)(cyB * inv_s), 0), W - 1);
        int cellA = gyA * W + gxA, cellB = gyB * W + gxB;

        float trA0 = (cxA - (float)gxA * s) * inv_s;
        float trA1 = (cyA - (float)gyA * s) * inv_s;
        float trA2 = (ax2 - ax1) * inv_s;
        float trA3 = (ay2 - ay1) * inv_s;
        float trB0 = (cxB - (float)gxB * s) * inv_s;
        float trB1 = (cyB - (float)gyB * s) * inv_s;
        float trB2 = (bx2 - bx1) * inv_s;
        float trB3 = (by2 - by1) * inv_s;

        // gather: 4 independent loads in flight per thread
        const float* rpA = rp0 + (size_t)b0 * 64 * HW + cellA;
        const float* rpB = rp0 + (size_t)(b0 + 16) * 64 * HW + cellB;
        float pA0 = rpA[(size_t)lane * HW];
        float pA1 = rpA[(size_t)(lane + 32) * HW];
        float pB0 = rpB[(size_t)lane * HW];
        float pB1 = rpB[(size_t)(lane + 32) * HW];

        float tAa = (lane < 16) ? trA0 : trA1;
        float tAb = (lane < 16) ? trA2 : trA3;
        float tBa = (lane < 16) ? trB0 : trB1;
        float tBb = (lane < 16) ? trB2 : trB3;

        float dflA = fabsf(pA0 - tAa) + fabsf(pA1 - tAb);
        float dflB = fabsf(pB0 - tBa) + fabsf(pB1 - tBb);
        #pragma unroll
        for (int off = 16; off > 0; off >>= 1) {
            dflA += __shfl_xor_sync(0xffffffffu, dflA, off);
            dflB += __shfl_xor_sync(0xffffffffu, dflB, off);
        }

        float sA0 = pA0, sA1 = pA1, sB0 = pB0, sB1 = pB1;
        #pragma unroll
        for (int off = 8; off > 0; off >>= 1) {
            sA0 += __shfl_xor_sync(0xffffffffu, sA0, off, 16);
            sA1 += __shfl_xor_sync(0xffffffffu, sA1, off, 16);
            sB0 += __shfl_xor_sync(0xffffffffu, sB0, off, 16);
            sB1 += __shfl_xor_sync(0xffffffffu, sB1, off, 16);
        }
        float bpA = 0.0f, bpB = 0.0f;
        if ((lane & 15) == 0) {
            bpA = fabsf(sA0 * (1.0f / RM) - tAa) + fabsf(sA1 * (1.0f / RM) - tAb);
            bpB = fabsf(sB0 * (1.0f / RM) - tBa) + fabsf(sB1 * (1.0f / RM) - tBb);
        }
        bpA += __shfl_xor_sync(0xffffffffu, bpA, 16);
        bpB += __shfl_xor_sync(0xffffffffu, bpB, 16);

        float ia = 0.f, ib = 0.f, id = 0.f;
        if (lane == 0) {
            float invHW = 1.0f / (float)HW;
            if (vA) {
                const float* cc = cp + (size_t)b0 * NCLS * HW + (size_t)cellA * NCLS;
                ia += (cc[0] - cc[cidA]) * invHW;
                ib += bpA * 0.25f;
                id += dflA * (1.0f / 64.0f);
            }
            if (vB) {
                const float* cc = cp + (size_t)(b0 + 16) * NCLS * HW + (size_t)cellB * NCLS;
                ia += (cc[0] - cc[cidB]) * invHW;
                ib += bpB * 0.25f;
                id += dflB * (1.0f / 64.0f);
            }
            s24[wrp] = ia; s24[8 + wrp] = ib; s24[16 + wrp] = id;
        }
        __syncthreads();
        if (tid == 0) {
            float a = 0.f, bb = 0.f, d = 0.f;
            #pragma unroll
            for (int i = 0; i < 8; i++) { a += s24[i]; bb += s24[8+i]; d += s24[16+i]; }
            int slot = bid & (NSLOT - 1);
            atomicAdd(&g_adjS[slot], a);
            atomicAdd(&g_boxS[slot], bb);
            atomicAdd(&g_dflS[slot], d);
        }
    }

    // ---------------- grid-completion handshake ----------------
    __syncthreads();
    __threadfence();
    if (tid == 0) {
        unsigned int old = atomicAdd(&g_count, 1u);
        s_last = (old == NB_TOT - 1) ? 1 : 0;
    }
    __syncthreads();
    if (!s_last) return;

    // ---------------- finalize (last block only) ----------------
    if (tid < BSZ) {
        int cnt = 0;
        for (int n = 0; n < NTGT; n++)
            cnt += (targets[(tid * NTGT + n) * 5] >= 0.0f) ? 1 : 0;
        fnv[tid] = (float)cnt;
    }
    __syncthreads();

    float clsP = 0.f, boxP = 0.f, dflP = 0.f;
    if (tid < NLVL * BSZ)
        clsP = __ldcg(&g_base[tid]) * c_invHW[tid >> 5] * fnv[tid & 31];
    else if (tid < NLVL * BSZ + NSLOT)
        clsP = __ldcg(&g_adjS[tid - NLVL * BSZ]);
    if (tid < NSLOT) {
        boxP = __ldcg(&g_boxS[tid]);
        dflP = __ldcg(&g_dflS[tid]);
    }
    #pragma unroll
    for (int off = 16; off > 0; off >>= 1) {
        clsP += __shfl_xor_sync(0xffffffffu, clsP, off);
        boxP += __shfl_xor_sync(0xffffffffu, boxP, off);
        dflP += __shfl_xor_sync(0xffffffffu, dflP, off);
    }
    if (lane == 0) { s24[wrp] = clsP; s24[8 + wrp] = boxP; s24[16 + wrp] = dflP; }
    __syncthreads();
    if (tid == 0) {
        float cls = 0.f, box = 0.f, dfl = 0.f;
        #pragma unroll
        for (int i = 0; i < 8; i++) { cls += s24[i]; box += s24[8+i]; dfl += s24[16+i]; }
        out[0] = 0.3f * cls + 8.0f * box + 1.5f * dfl;
        out[1] = cls;
        out[2] = box;
        out[3] = dfl;
        g_count = 0u;
    }
    if (tid < NLVL * BSZ) g_base[tid] = 0.0f;
    if (tid < NSLOT) { g_adjS[tid] = 0.0f; g_boxS[tid] = 0.0f; g_dflS[tid] = 0.0f; }
}

// ---------------------------------------------------------------------------
extern "C" void kernel_launch(void* const* d_in, const int* in_sizes, int n_in,
                              void* d_out, int out_size) {
    const float* cls[NLVL];
    const float* reg[NLVL];
    bool interleaved = (in_sizes[1] > in_sizes[0]);
    if (interleaved) {
        for (int l = 0; l < NLVL; l++) {
            cls[l] = (const float*)d_in[2 * l];
            reg[l] = (const float*)d_in[2 * l + 1];
        }
    } else {
        for (int l = 0; l < NLVL; l++) {
            cls[l] = (const float*)d_in[l];
            reg[l] = (const float*)d_in[NLVL + l];
        }
    }
    const float* targets = (const float*)d_in[8];
    float* out = (float*)d_out;

    yolo_fused_kernel<<<NB_TOT, 256>>>(cls[0], cls[1], cls[2], cls[3],
                                       reg[0], reg[1], reg[2], reg[3],
                                       targets, out);
}